// round 1
// baseline (speedup 1.0000x reference)
#include <cuda_runtime.h>
#include <math.h>
#include <stdint.h>

#define BSZ  4
#define QLEN 2048
#define DIM  1024
#define NH   16
#define DH   64
#define MTOT (BSZ * QLEN)   // 8192

// Scratch (allocation-free rule: __device__ globals)
__device__ float g_q[BSZ * NH * QLEN * DH];
__device__ float g_k[BSZ * NH * QLEN * DH];
__device__ float g_v[BSZ * NH * QLEN * DH];
__device__ float g_ctx[MTOT * DIM];

// ---------------------------------------------------------------------------
// Kernel 1: QKV projections.  C = (A @ W^T + b) * scale, scattered to [b,h,t,d]
// A: [8192,1024] row-major (x), W: [1024,1024] row-major.
// Tile 64x64x32, 256 threads, 4x4 micro-tile per thread.
// ---------------------------------------------------------------------------
__global__ __launch_bounds__(256) void qkv_kernel(
    const float* __restrict__ x,
    const float* __restrict__ wq, const float* __restrict__ bq,
    const float* __restrict__ wk, const float* __restrict__ bk,
    const float* __restrict__ wv, const float* __restrict__ bv)
{
    const int z = blockIdx.z;
    const float* W = (z == 0) ? wq : (z == 1) ? wk : wv;
    const float* B = (z == 0) ? bq : (z == 1) ? bk : bv;
    float* out     = (z == 0) ? g_q : (z == 1) ? g_k : g_v;
    const float scale = (z == 0) ? 0.125f : 1.0f;   // 1/sqrt(DH)

    __shared__ float As[32][64];   // As[k][m] (transposed)
    __shared__ float Ws[32][64];   // Ws[k][n] (transposed)

    const int m0  = blockIdx.y * 64;
    const int n0  = blockIdx.x * 64;
    const int tid = threadIdx.x;
    const int tx  = tid & 15;
    const int ty  = tid >> 4;

    float acc[4][4] = {};

    for (int k0 = 0; k0 < DIM; k0 += 32) {
        #pragma unroll
        for (int l = 0; l < 2; l++) {
            int idx = tid + l * 256;       // 0..511
            int row = idx >> 3;            // 0..63
            int c4  = (idx & 7) * 4;       // 0,4,...,28
            float4 a = *(const float4*)&x[(size_t)(m0 + row) * DIM + k0 + c4];
            As[c4 + 0][row] = a.x; As[c4 + 1][row] = a.y;
            As[c4 + 2][row] = a.z; As[c4 + 3][row] = a.w;
            float4 w = *(const float4*)&W[(size_t)(n0 + row) * DIM + k0 + c4];
            Ws[c4 + 0][row] = w.x; Ws[c4 + 1][row] = w.y;
            Ws[c4 + 2][row] = w.z; Ws[c4 + 3][row] = w.w;
        }
        __syncthreads();
        #pragma unroll 8
        for (int k = 0; k < 32; k++) {
            float4 a4 = *(const float4*)&As[k][ty * 4];
            float4 b4 = *(const float4*)&Ws[k][tx * 4];
            float a[4] = {a4.x, a4.y, a4.z, a4.w};
            float b[4] = {b4.x, b4.y, b4.z, b4.w};
            #pragma unroll
            for (int i = 0; i < 4; i++)
                #pragma unroll
                for (int j = 0; j < 4; j++)
                    acc[i][j] = fmaf(a[i], b[j], acc[i][j]);
        }
        __syncthreads();
    }

    // Epilogue: n-tile (64) == exactly one head. out[b,h,t,d].
    const int n = n0 + tx * 4;
    const int h = n >> 6;
    const int d = n & 63;
    float4 bias = *(const float4*)&B[n];
    #pragma unroll
    for (int i = 0; i < 4; i++) {
        int m = m0 + ty * 4 + i;
        int b = m >> 11;          // / QLEN
        int t = m & 2047;
        float4 r;
        r.x = (acc[i][0] + bias.x) * scale;
        r.y = (acc[i][1] + bias.y) * scale;
        r.z = (acc[i][2] + bias.z) * scale;
        r.w = (acc[i][3] + bias.w) * scale;
        *(float4*)&out[(size_t)(((b * NH + h) * QLEN) + t) * DH + d] = r;
    }
}

// ---------------------------------------------------------------------------
// Kernel 2: flash attention, one (b,h) x 64-query-tile per CTA.
// smem (dynamic, 66048 B): Qts[64][64] (Q^T), Kts[64][64] (K^T),
// Vs[64][64] (natural), Ps[64][65], mb[64].
// ---------------------------------------------------------------------------
#define ATTN_SMEM_FLOATS (4096 * 3 + 64 * 65 + 64)
#define ATTN_SMEM_BYTES  (ATTN_SMEM_FLOATS * 4)

__global__ __launch_bounds__(256) void attn_kernel(const int* __restrict__ mask)
{
    extern __shared__ float sm[];
    float* Qts = sm;                    // Qts[d][r]
    float* Kts = sm + 4096;             // Kts[d][c]
    float* Vs  = sm + 8192;             // Vs[c][d]
    float* Ps  = sm + 12288;            // Ps[r][c], stride 65
    float* mb  = sm + 12288 + 64 * 65;  // [64]

    const int bh  = blockIdx.y;         // b*NH + h
    const int b   = bh >> 4;
    const int h   = bh & 15;
    const int q0  = blockIdx.x * 64;
    const int tid = threadIdx.x;
    const int tx  = tid & 15;
    const int ty  = tid >> 4;

    const float* Qg = g_q + (size_t)bh * QLEN * DH;
    const float* Kg = g_k + (size_t)bh * QLEN * DH;
    const float* Vg = g_v + (size_t)bh * QLEN * DH;

    // Load Q tile, transposed: Qts[d][r]
    #pragma unroll
    for (int l = 0; l < 4; l++) {
        int idx = tid + l * 256;        // 0..1023
        int r   = idx >> 4;             // 0..63
        int c4  = (idx & 15) * 4;       // 0..60
        float4 a = *(const float4*)&Qg[(size_t)(q0 + r) * DH + c4];
        Qts[(c4 + 0) * 64 + r] = a.x;
        Qts[(c4 + 1) * 64 + r] = a.y;
        Qts[(c4 + 2) * 64 + r] = a.z;
        Qts[(c4 + 3) * 64 + r] = a.w;
    }

    float o[4][4] = {};
    float rm[4], rl[4];
    #pragma unroll
    for (int i = 0; i < 4; i++) { rm[i] = -1e30f; rl[i] = 0.0f; }

    for (int kt = 0; kt < QLEN / 64; kt++) {
        const int kbase = kt * 64;
        __syncthreads();  // previous P@V reads done before overwriting K/V tiles

        #pragma unroll
        for (int l = 0; l < 4; l++) {
            int idx = tid + l * 256;
            int r   = idx >> 4;
            int c4  = (idx & 15) * 4;
            float4 kk = *(const float4*)&Kg[(size_t)(kbase + r) * DH + c4];
            Kts[(c4 + 0) * 64 + r] = kk.x;
            Kts[(c4 + 1) * 64 + r] = kk.y;
            Kts[(c4 + 2) * 64 + r] = kk.z;
            Kts[(c4 + 3) * 64 + r] = kk.w;
            float4 vv = *(const float4*)&Vg[(size_t)(kbase + r) * DH + c4];
            *(float4*)&Vs[r * 64 + c4] = vv;
        }
        if (tid < 64)
            mb[tid] = (mask[b * QLEN + kbase + tid] == 0) ? -1e30f : 0.0f;
        __syncthreads();

        // S = Q @ K^T  (4x4 per thread, rows ty*4.., cols tx*4..)
        float s[4][4] = {};
        #pragma unroll 8
        for (int d = 0; d < 64; d++) {
            float4 a4 = *(const float4*)&Qts[d * 64 + ty * 4];
            float4 b4 = *(const float4*)&Kts[d * 64 + tx * 4];
            float a[4] = {a4.x, a4.y, a4.z, a4.w};
            float bb[4] = {b4.x, b4.y, b4.z, b4.w};
            #pragma unroll
            for (int i = 0; i < 4; i++)
                #pragma unroll
                for (int j = 0; j < 4; j++)
                    s[i][j] = fmaf(a[i], bb[j], s[i][j]);
        }

        float bm[4];
        #pragma unroll
        for (int j = 0; j < 4; j++) bm[j] = mb[tx * 4 + j];

        // Online softmax update (row stats reduced across the 16 tx lanes)
        #pragma unroll
        for (int i = 0; i < 4; i++) {
            float mx = -1e30f;
            #pragma unroll
            for (int j = 0; j < 4; j++) {
                s[i][j] += bm[j];
                mx = fmaxf(mx, s[i][j]);
            }
            #pragma unroll
            for (int off = 1; off < 16; off <<= 1)
                mx = fmaxf(mx, __shfl_xor_sync(0xffffffffu, mx, off));
            float mnew  = fmaxf(rm[i], mx);
            float alpha = __expf(rm[i] - mnew);
            float rs = 0.0f;
            #pragma unroll
            for (int j = 0; j < 4; j++) {
                float p = __expf(s[i][j] - mnew);
                s[i][j] = p;
                rs += p;
            }
            #pragma unroll
            for (int off = 1; off < 16; off <<= 1)
                rs += __shfl_xor_sync(0xffffffffu, rs, off);
            rl[i] = rl[i] * alpha + rs;
            rm[i] = mnew;
            #pragma unroll
            for (int j = 0; j < 4; j++) o[i][j] *= alpha;
        }

        // P -> smem (natural layout, stride 65)
        #pragma unroll
        for (int i = 0; i < 4; i++)
            #pragma unroll
            for (int j = 0; j < 4; j++)
                Ps[(ty * 4 + i) * 65 + tx * 4 + j] = s[i][j];
        __syncthreads();

        // O += P @ V
        #pragma unroll 8
        for (int c = 0; c < 64; c++) {
            float4 v4 = *(const float4*)&Vs[c * 64 + tx * 4];
            float pv[4];
            #pragma unroll
            for (int i = 0; i < 4; i++) pv[i] = Ps[(ty * 4 + i) * 65 + c];
            #pragma unroll
            for (int i = 0; i < 4; i++) {
                o[i][0] = fmaf(pv[i], v4.x, o[i][0]);
                o[i][1] = fmaf(pv[i], v4.y, o[i][1]);
                o[i][2] = fmaf(pv[i], v4.z, o[i][2]);
                o[i][3] = fmaf(pv[i], v4.w, o[i][3]);
            }
        }
    }

    // Epilogue: ctx[b, t, h*DH + d] (natural [8192,1024] layout)
    #pragma unroll
    for (int i = 0; i < 4; i++) {
        int t = q0 + ty * 4 + i;
        float inv = 1.0f / rl[i];
        float4 r;
        r.x = o[i][0] * inv;
        r.y = o[i][1] * inv;
        r.z = o[i][2] * inv;
        r.w = o[i][3] * inv;
        *(float4*)&g_ctx[(size_t)(b * QLEN + t) * DIM + h * DH + tx * 4] = r;
    }
}

// ---------------------------------------------------------------------------
// Kernel 3: output projection.  out = ctx @ wo^T + bo, [8192,1024] row-major.
// ---------------------------------------------------------------------------
__global__ __launch_bounds__(256) void out_kernel(
    const float* __restrict__ wo, const float* __restrict__ bo,
    float* __restrict__ out)
{
    __shared__ float As[32][64];
    __shared__ float Ws[32][64];

    const int m0  = blockIdx.y * 64;
    const int n0  = blockIdx.x * 64;
    const int tid = threadIdx.x;
    const int tx  = tid & 15;
    const int ty  = tid >> 4;

    float acc[4][4] = {};

    for (int k0 = 0; k0 < DIM; k0 += 32) {
        #pragma unroll
        for (int l = 0; l < 2; l++) {
            int idx = tid + l * 256;
            int row = idx >> 3;
            int c4  = (idx & 7) * 4;
            float4 a = *(const float4*)&g_ctx[(size_t)(m0 + row) * DIM + k0 + c4];
            As[c4 + 0][row] = a.x; As[c4 + 1][row] = a.y;
            As[c4 + 2][row] = a.z; As[c4 + 3][row] = a.w;
            float4 w = *(const float4*)&wo[(size_t)(n0 + row) * DIM + k0 + c4];
            Ws[c4 + 0][row] = w.x; Ws[c4 + 1][row] = w.y;
            Ws[c4 + 2][row] = w.z; Ws[c4 + 3][row] = w.w;
        }
        __syncthreads();
        #pragma unroll 8
        for (int k = 0; k < 32; k++) {
            float4 a4 = *(const float4*)&As[k][ty * 4];
            float4 b4 = *(const float4*)&Ws[k][tx * 4];
            float a[4] = {a4.x, a4.y, a4.z, a4.w};
            float b[4] = {b4.x, b4.y, b4.z, b4.w};
            #pragma unroll
            for (int i = 0; i < 4; i++)
                #pragma unroll
                for (int j = 0; j < 4; j++)
                    acc[i][j] = fmaf(a[i], b[j], acc[i][j]);
        }
        __syncthreads();
    }

    const int n = n0 + tx * 4;
    float4 bias = *(const float4*)&bo[n];
    #pragma unroll
    for (int i = 0; i < 4; i++) {
        int m = m0 + ty * 4 + i;
        float4 r;
        r.x = acc[i][0] + bias.x;
        r.y = acc[i][1] + bias.y;
        r.z = acc[i][2] + bias.z;
        r.w = acc[i][3] + bias.w;
        *(float4*)&out[(size_t)m * DIM + n] = r;
    }
}

// ---------------------------------------------------------------------------
extern "C" void kernel_launch(void* const* d_in, const int* in_sizes, int n_in,
                              void* d_out, int out_size)
{
    const float* x    = (const float*)d_in[0];
    const int*   mask = (const int*)  d_in[1];
    const float* wq   = (const float*)d_in[2];
    const float* bq   = (const float*)d_in[3];
    const float* wk   = (const float*)d_in[4];
    const float* bk   = (const float*)d_in[5];
    const float* wv   = (const float*)d_in[6];
    const float* bv   = (const float*)d_in[7];
    const float* wo   = (const float*)d_in[8];
    const float* bo   = (const float*)d_in[9];
    float* out = (float*)d_out;

    // QKV projections
    dim3 g1(DIM / 64, MTOT / 64, 3);
    qkv_kernel<<<g1, 256>>>(x, wq, bq, wk, bk, wv, bv);

    // Attention (dynamic smem > 48KB)
    cudaFuncSetAttribute(attn_kernel,
                         cudaFuncAttributeMaxDynamicSharedMemorySize,
                         ATTN_SMEM_BYTES);
    dim3 g2(QLEN / 64, BSZ * NH);
    attn_kernel<<<g2, 256, ATTN_SMEM_BYTES>>>(mask);

    // Output projection
    dim3 g3(DIM / 64, MTOT / 64);
    out_kernel<<<g3, 256>>>(wo, bo, out);
}

// round 2
// speedup vs baseline: 4.1936x; 4.1936x over previous
#include <cuda_runtime.h>
#include <stdint.h>

#define BSZ  4
#define QLEN 2048
#define DIM  1024
#define NH   16
#define DH   64
#define MTOT (BSZ * QLEN)   // 8192

// Scratch (allocation-free rule: __device__ globals)
__device__ float g_q[BSZ * NH * QLEN * DH];
__device__ float g_k[BSZ * NH * QLEN * DH];
__device__ float g_v[BSZ * NH * QLEN * DH];
__device__ float g_ctx[MTOT * DIM];

__device__ __forceinline__ uint32_t f2tf(float f) {
    uint32_t r;
    asm("cvt.rna.tf32.f32 %0, %1;" : "=r"(r) : "f"(f));
    return r;
}

// D = A(16x8,row) * B(8x8,col) + D, tf32, fp32 accum
__device__ __forceinline__ void mma8(float c[4], const uint32_t a[4], const uint32_t b[2]) {
    asm volatile(
        "mma.sync.aligned.m16n8k8.row.col.f32.tf32.tf32.f32 "
        "{%0,%1,%2,%3}, {%4,%5,%6,%7}, {%8,%9}, {%0,%1,%2,%3};\n"
        : "+f"(c[0]), "+f"(c[1]), "+f"(c[2]), "+f"(c[3])
        : "r"(a[0]), "r"(a[1]), "r"(a[2]), "r"(a[3]), "r"(b[0]), "r"(b[1]));
}

// ---------------------------------------------------------------------------
// Generic GEMM: C = A[MTOT,1024] @ W[1024,1024]^T (+ bias) (* scale)
// BM=128, BN=128, BK=16, 256 threads, 8 warps (2m x 4n), warp tile 64x32.
// scatter=1: write to [b,h,t,d] layout; scatter=0: row-major [m][n].
// ---------------------------------------------------------------------------
#define SKA 20   // smem k-stride (16 + 4 pad) -> conflict-free frag loads

__global__ __launch_bounds__(256, 2) void gemm_tf32(
    const float* __restrict__ A, const float* __restrict__ W,
    const float* __restrict__ bias, float* __restrict__ out,
    float scale, int scatter)
{
    __shared__ uint32_t As[2][128 * SKA];
    __shared__ uint32_t Bs[2][128 * SKA];

    const int m0 = blockIdx.y * 128, n0 = blockIdx.x * 128;
    const int tid = threadIdx.x, lane = tid & 31, wid = tid >> 5;
    const int wm = (wid >> 2) * 64, wn = (wid & 3) * 32;
    const int g = lane >> 2, t = lane & 3;

    const int arow0 = tid >> 2;          // rows arow0, arow0+64
    const int ac4   = (tid & 3) * 4;

    float4 pa[2], pw[2];
    #pragma unroll
    for (int l = 0; l < 2; l++) {
        int row = arow0 + l * 64;
        pa[l] = *(const float4*)&A[(size_t)(m0 + row) * DIM + ac4];
        pw[l] = *(const float4*)&W[(size_t)(n0 + row) * DIM + ac4];
    }
    // store tile 0
    #pragma unroll
    for (int l = 0; l < 2; l++) {
        int row = arow0 + l * 64;
        uint32_t* p = &As[0][row * SKA + ac4];
        p[0] = f2tf(pa[l].x); p[1] = f2tf(pa[l].y); p[2] = f2tf(pa[l].z); p[3] = f2tf(pa[l].w);
        uint32_t* q = &Bs[0][row * SKA + ac4];
        q[0] = f2tf(pw[l].x); q[1] = f2tf(pw[l].y); q[2] = f2tf(pw[l].z); q[3] = f2tf(pw[l].w);
    }

    float c[4][4][4] = {};

    #pragma unroll 1
    for (int kt = 0; kt < DIM / 16; kt++) {
        const int buf = kt & 1;
        __syncthreads();
        if (kt + 1 < DIM / 16) {
            const int k0 = (kt + 1) * 16;
            #pragma unroll
            for (int l = 0; l < 2; l++) {
                int row = arow0 + l * 64;
                pa[l] = *(const float4*)&A[(size_t)(m0 + row) * DIM + k0 + ac4];
                pw[l] = *(const float4*)&W[(size_t)(n0 + row) * DIM + k0 + ac4];
            }
        }
        #pragma unroll
        for (int ks = 0; ks < 2; ks++) {
            const int kb = ks * 8;
            uint32_t af[4][4], bf[4][2];
            #pragma unroll
            for (int mt = 0; mt < 4; mt++) {
                int r = wm + mt * 16;
                const uint32_t* p0 = &As[buf][(r + g) * SKA + kb + t];
                const uint32_t* p1 = &As[buf][(r + g + 8) * SKA + kb + t];
                af[mt][0] = p0[0]; af[mt][1] = p1[0];
                af[mt][2] = p0[4]; af[mt][3] = p1[4];
            }
            #pragma unroll
            for (int nt = 0; nt < 4; nt++) {
                int n = wn + nt * 8;
                const uint32_t* p = &Bs[buf][(n + g) * SKA + kb + t];
                bf[nt][0] = p[0]; bf[nt][1] = p[4];
            }
            #pragma unroll
            for (int mt = 0; mt < 4; mt++)
                #pragma unroll
                for (int nt = 0; nt < 4; nt++)
                    mma8(c[mt][nt], af[mt], bf[nt]);
        }
        if (kt + 1 < DIM / 16) {
            #pragma unroll
            for (int l = 0; l < 2; l++) {
                int row = arow0 + l * 64;
                uint32_t* p = &As[buf ^ 1][row * SKA + ac4];
                p[0] = f2tf(pa[l].x); p[1] = f2tf(pa[l].y); p[2] = f2tf(pa[l].z); p[3] = f2tf(pa[l].w);
                uint32_t* q = &Bs[buf ^ 1][row * SKA + ac4];
                q[0] = f2tf(pw[l].x); q[1] = f2tf(pw[l].y); q[2] = f2tf(pw[l].z); q[3] = f2tf(pw[l].w);
            }
        }
    }

    // Epilogue
    #pragma unroll
    for (int mt = 0; mt < 4; mt++) {
        #pragma unroll
        for (int nt = 0; nt < 4; nt++) {
            const int n = n0 + wn + nt * 8 + 2 * t;
            const float2 bb = *(const float2*)&bias[n];
            #pragma unroll
            for (int rr = 0; rr < 2; rr++) {
                const int m = m0 + wm + mt * 16 + g + rr * 8;
                float2 v;
                v.x = (c[mt][nt][rr * 2 + 0] + bb.x) * scale;
                v.y = (c[mt][nt][rr * 2 + 1] + bb.y) * scale;
                if (scatter) {
                    int b = m >> 11, ts = m & 2047;
                    int h = n >> 6, d = n & 63;
                    *(float2*)&out[(size_t)(((b * NH + h) * QLEN) + ts) * DH + d] = v;
                } else {
                    *(float2*)&out[(size_t)m * DIM + n] = v;
                }
            }
        }
    }
}

// ---------------------------------------------------------------------------
// Flash attention, tf32 tensor cores.
// Block: 128 queries, 4 warps (warp = 32q x 64k), loop over 64-key tiles.
// Smem (u32 words): Qs 128x68, Ks 64x68, Vs 64x72, Ps 128x72, mb 64.
// ---------------------------------------------------------------------------
#define OFF_Q  0
#define OFF_K  (128 * 68)                 // 8704
#define OFF_V  (OFF_K + 64 * 68)          // 13056
#define OFF_P  (OFF_V + 64 * 72)          // 17664
#define OFF_MB (OFF_P + 128 * 72)         // 26880
#define ATTN_SMEM_BYTES ((OFF_MB + 64) * 4)   // 107776

__global__ __launch_bounds__(128, 2) void attn_tf32(const int* __restrict__ mask)
{
    extern __shared__ uint32_t sm[];
    uint32_t* Qs = sm + OFF_Q;
    uint32_t* Ks = sm + OFF_K;
    uint32_t* Vs = sm + OFF_V;
    uint32_t* Ps = sm + OFF_P;
    float*    mb = (float*)(sm + OFF_MB);

    const int bh = blockIdx.y, b = bh >> 4, h = bh & 15;
    const int q0 = blockIdx.x * 128;
    const int tid = threadIdx.x, lane = tid & 31, wid = tid >> 5;
    const int g = lane >> 2, t = lane & 3;
    const int qw = wid * 32;

    const float* Qg = g_q + (size_t)bh * QLEN * DH;
    const float* Kg = g_k + (size_t)bh * QLEN * DH;
    const float* Vg = g_v + (size_t)bh * QLEN * DH;

    // Load Q tile (128x64) once
    #pragma unroll
    for (int l = 0; l < 16; l++) {
        int idx = tid + l * 128;
        int row = idx >> 4, c4 = (idx & 15) * 4;
        float4 v = *(const float4*)&Qg[(size_t)(q0 + row) * DH + c4];
        uint32_t* p = &Qs[row * 68 + c4];
        p[0] = f2tf(v.x); p[1] = f2tf(v.y); p[2] = f2tf(v.z); p[3] = f2tf(v.w);
    }

    float o[2][8][4] = {};
    float rm[2][2], rl[2][2];
    #pragma unroll
    for (int mt = 0; mt < 2; mt++)
        #pragma unroll
        for (int r = 0; r < 2; r++) { rm[mt][r] = -1e30f; rl[mt][r] = 0.0f; }

    #pragma unroll 1
    for (int kt = 0; kt < QLEN / 64; kt++) {
        const int kbase = kt * 64;
        __syncthreads();   // prior P@V reads of Ks/Vs complete
        #pragma unroll
        for (int l = 0; l < 8; l++) {
            int idx = tid + l * 128;
            int row = idx >> 4, c4 = (idx & 15) * 4;
            float4 kv = *(const float4*)&Kg[(size_t)(kbase + row) * DH + c4];
            uint32_t* p = &Ks[row * 68 + c4];
            p[0] = f2tf(kv.x); p[1] = f2tf(kv.y); p[2] = f2tf(kv.z); p[3] = f2tf(kv.w);
            float4 vv = *(const float4*)&Vg[(size_t)(kbase + row) * DH + c4];
            uint32_t* q = &Vs[row * 72 + c4];
            q[0] = f2tf(vv.x); q[1] = f2tf(vv.y); q[2] = f2tf(vv.z); q[3] = f2tf(vv.w);
        }
        if (tid < 64)
            mb[tid] = (mask[b * QLEN + kbase + tid] == 0) ? -1e30f : 0.0f;
        __syncthreads();

        // S = Q @ K^T  (warp: 32q x 64k)
        float s[2][8][4] = {};
        #pragma unroll
        for (int ks = 0; ks < 8; ks++) {
            const int kb = ks * 8;
            uint32_t af[2][4];
            #pragma unroll
            for (int mt = 0; mt < 2; mt++) {
                int r = qw + mt * 16;
                const uint32_t* p0 = &Qs[(r + g) * 68 + kb + t];
                const uint32_t* p1 = &Qs[(r + g + 8) * 68 + kb + t];
                af[mt][0] = p0[0]; af[mt][1] = p1[0];
                af[mt][2] = p0[4]; af[mt][3] = p1[4];
            }
            uint32_t bf[8][2];
            #pragma unroll
            for (int nt = 0; nt < 8; nt++) {
                const uint32_t* p = &Ks[(nt * 8 + g) * 68 + kb + t];
                bf[nt][0] = p[0]; bf[nt][1] = p[4];
            }
            #pragma unroll
            for (int mt = 0; mt < 2; mt++)
                #pragma unroll
                for (int nt = 0; nt < 8; nt++)
                    mma8(s[mt][nt], af[mt], bf[nt]);
        }

        // mask add
        #pragma unroll
        for (int nt = 0; nt < 8; nt++) {
            float b0 = mb[nt * 8 + 2 * t];
            float b1 = mb[nt * 8 + 2 * t + 1];
            #pragma unroll
            for (int mt = 0; mt < 2; mt++) {
                s[mt][nt][0] += b0; s[mt][nt][1] += b1;
                s[mt][nt][2] += b0; s[mt][nt][3] += b1;
            }
        }

        // online softmax (rows owned by 4 t-lanes: shfl xor 1,2)
        #pragma unroll
        for (int mt = 0; mt < 2; mt++) {
            #pragma unroll
            for (int r = 0; r < 2; r++) {
                float mx = -1e30f;
                #pragma unroll
                for (int nt = 0; nt < 8; nt++)
                    mx = fmaxf(mx, fmaxf(s[mt][nt][r * 2], s[mt][nt][r * 2 + 1]));
                mx = fmaxf(mx, __shfl_xor_sync(0xffffffffu, mx, 1));
                mx = fmaxf(mx, __shfl_xor_sync(0xffffffffu, mx, 2));
                float mnew  = fmaxf(rm[mt][r], mx);
                float alpha = __expf(rm[mt][r] - mnew);
                rm[mt][r] = mnew;
                float rs = 0.0f;
                #pragma unroll
                for (int nt = 0; nt < 8; nt++) {
                    float p0 = __expf(s[mt][nt][r * 2]     - mnew);
                    float p1 = __expf(s[mt][nt][r * 2 + 1] - mnew);
                    s[mt][nt][r * 2] = p0; s[mt][nt][r * 2 + 1] = p1;
                    rs += p0 + p1;
                }
                rs += __shfl_xor_sync(0xffffffffu, rs, 1);
                rs += __shfl_xor_sync(0xffffffffu, rs, 2);
                rl[mt][r] = rl[mt][r] * alpha + rs;
                #pragma unroll
                for (int nt = 0; nt < 8; nt++) {
                    o[mt][nt][r * 2]     *= alpha;
                    o[mt][nt][r * 2 + 1] *= alpha;
                }
            }
        }

        // P -> smem (per-warp private rows)
        #pragma unroll
        for (int mt = 0; mt < 2; mt++)
            #pragma unroll
            for (int nt = 0; nt < 8; nt++)
                #pragma unroll
                for (int i = 0; i < 4; i++) {
                    int row = qw + mt * 16 + g + (i >> 1) * 8;
                    Ps[row * 72 + nt * 8 + 2 * t + (i & 1)] = f2tf(s[mt][nt][i]);
                }
        __syncwarp();

        // O += P @ V
        #pragma unroll
        for (int ks = 0; ks < 8; ks++) {
            const int kb = ks * 8;
            uint32_t af[2][4];
            #pragma unroll
            for (int mt = 0; mt < 2; mt++) {
                int r = qw + mt * 16;
                const uint32_t* p0 = &Ps[(r + g) * 72 + kb + t];
                const uint32_t* p1 = &Ps[(r + g + 8) * 72 + kb + t];
                af[mt][0] = p0[0]; af[mt][1] = p1[0];
                af[mt][2] = p0[4]; af[mt][3] = p1[4];
            }
            uint32_t bf[8][2];
            #pragma unroll
            for (int nt = 0; nt < 8; nt++) {
                bf[nt][0] = Vs[(kb + t) * 72 + nt * 8 + g];
                bf[nt][1] = Vs[(kb + t + 4) * 72 + nt * 8 + g];
            }
            #pragma unroll
            for (int mt = 0; mt < 2; mt++)
                #pragma unroll
                for (int nt = 0; nt < 8; nt++)
                    mma8(o[mt][nt], af[mt], bf[nt]);
        }
    }

    // Epilogue: ctx[b, t, h*64 + d]
    #pragma unroll
    for (int mt = 0; mt < 2; mt++) {
        #pragma unroll
        for (int r = 0; r < 2; r++) {
            float inv = 1.0f / rl[mt][r];
            int row = q0 + qw + mt * 16 + g + r * 8;
            #pragma unroll
            for (int nt = 0; nt < 8; nt++) {
                float2 v;
                v.x = o[mt][nt][r * 2]     * inv;
                v.y = o[mt][nt][r * 2 + 1] * inv;
                *(float2*)&g_ctx[(size_t)(b * QLEN + row) * DIM + h * DH + nt * 8 + 2 * t] = v;
            }
        }
    }
}

// ---------------------------------------------------------------------------
extern "C" void kernel_launch(void* const* d_in, const int* in_sizes, int n_in,
                              void* d_out, int out_size)
{
    const float* x    = (const float*)d_in[0];
    const int*   mask = (const int*)  d_in[1];
    const float* wq   = (const float*)d_in[2];
    const float* bq   = (const float*)d_in[3];
    const float* wk   = (const float*)d_in[4];
    const float* bk   = (const float*)d_in[5];
    const float* wv   = (const float*)d_in[6];
    const float* bv   = (const float*)d_in[7];
    const float* wo   = (const float*)d_in[8];
    const float* bo   = (const float*)d_in[9];
    float* out = (float*)d_out;

    float *qp, *kp, *vp, *cp;
    cudaGetSymbolAddress((void**)&qp, g_q);
    cudaGetSymbolAddress((void**)&kp, g_k);
    cudaGetSymbolAddress((void**)&vp, g_v);
    cudaGetSymbolAddress((void**)&cp, g_ctx);

    cudaFuncSetAttribute(attn_tf32,
                         cudaFuncAttributeMaxDynamicSharedMemorySize,
                         ATTN_SMEM_BYTES);

    dim3 gp(DIM / 128, MTOT / 128);
    gemm_tf32<<<gp, 256>>>(x, wq, bq, qp, 0.125f, 1);
    gemm_tf32<<<gp, 256>>>(x, wk, bk, kp, 1.0f, 1);
    gemm_tf32<<<gp, 256>>>(x, wv, bv, vp, 1.0f, 1);

    dim3 ga(QLEN / 128, BSZ * NH);
    attn_tf32<<<ga, 128, ATTN_SMEM_BYTES>>>(mask);

    gemm_tf32<<<gp, 256>>>(cp, wo, bo, out, 1.0f, 0);
}